// round 1
// baseline (speedup 1.0000x reference)
#include <cuda_runtime.h>

#define TT 512
#define BB 4096
#define HH 16

// Scratch: y0 = concat(layer0 fwd, layer0 bwd) laid out [T][B][32] for coalesced
// per-timestep access in both producer and consumer. 268 MB, static device mem
// (allocation APIs are forbidden; __device__ globals are the sanctioned path).
__device__ float g_y0[(size_t)TT * BB * 32];

__device__ __forceinline__ float sigmoid_f(float x) {
    // 1/(1+e^-x): MUFU EX2 + MUFU RCP. ~1e-7 rel err, saturates correctly.
    return __fdividef(1.0f, 1.0f + __expf(-x));
}

__device__ __forceinline__ float tanh_f(float x) {
    // tanh(x) = (1 - e^{-2x}) / (1 + e^{-2x}); clamp so e never overflows to inf
    // (inf/inf -> NaN in the approx divide).
    x = fminf(fmaxf(x, -15.0f), 15.0f);
    float e = __expf(-2.0f * x);
    return __fdividef(1.0f - e, 1.0f + e);
}

// ---------------------------------------------------------------------------
// Kernel 1: layer 0, both directions (blockIdx.y selects direction).
// 16 threads per batch element; thread j owns hidden unit j, holds gate-row
// weight slices {j, j+16, j+32} of Whh in registers. h exchanged by shuffle.
// ---------------------------------------------------------------------------
__global__ void __launch_bounds__(128) gru_l0(
    const float* __restrict__ x,
    const float* __restrict__ WihF, const float* __restrict__ WhhF,
    const float* __restrict__ bihF, const float* __restrict__ bhhF,
    const float* __restrict__ WihB, const float* __restrict__ WhhB,
    const float* __restrict__ bihB, const float* __restrict__ bhhB)
{
    const int tid = threadIdx.x;
    const int j = tid & 15;          // hidden index
    const int e = tid >> 4;          // local batch element (0..7)
    const int b = blockIdx.x * 8 + e;
    const bool bwd = (blockIdx.y != 0);

    const float* Wih = bwd ? WihB : WihF;
    const float* Whh = bwd ? WhhB : WhhF;
    const float* bih = bwd ? bihB : bihF;
    const float* bhh = bwd ? bhhB : bhhF;

    float wr[16], wz[16], wn[16];
#pragma unroll
    for (int k = 0; k < 16; ++k) {
        wr[k] = Whh[(j)      * 16 + k];
        wz[k] = Whh[(j + 16) * 16 + k];
        wn[k] = Whh[(j + 32) * 16 + k];
    }
    const float wir = Wih[j], wiz = Wih[j + 16], win = Wih[j + 32];
    const float bir = bih[j], biz = bih[j + 16], bin_ = bih[j + 32];
    const float bhr = bhh[j], bhz = bhh[j + 16], bhn = bhh[j + 32];

    const float* xp = x + (size_t)b * TT;          // x is [B, T, 1]
    float* yp = g_y0 + (size_t)b * 32 + (bwd ? 16 : 0) + j;

    const int t0 = bwd ? TT - 1 : 0;
    const int dt = bwd ? -1 : 1;

    float h = 0.0f;
    float xv = xp[t0];
    int t = t0;
    for (int s = 0; s < TT; ++s) {
        // prefetch next x to hide global latency behind the FMA chain
        float xnext = (s + 1 < TT) ? xp[t + dt] : 0.0f;

        float ar = bhr, az = bhz, an = bhn;
#pragma unroll
        for (int k = 0; k < 16; ++k) {
            float hk = __shfl_sync(0xFFFFFFFFu, h, k, 16);
            ar = fmaf(wr[k], hk, ar);
            az = fmaf(wz[k], hk, az);
            an = fmaf(wn[k], hk, an);
        }
        float r = sigmoid_f(fmaf(xv, wir, bir) + ar);
        float z = sigmoid_f(fmaf(xv, wiz, biz) + az);
        float n = tanh_f(fmaf(r, an, fmaf(xv, win, bin_)));
        h = n + z * (h - n);                       // (1-z)*n + z*h

        yp[(size_t)t * (BB * 32)] = h;
        xv = xnext;
        t += dt;
    }
}

// ---------------------------------------------------------------------------
// Kernel 2: layer 1 forward over full T, reading y0 [T][B][32] coalesced.
// Thread j supplies y0[2j], y0[2j+1] via shuffle to its 16-lane group.
// Writes out[b][0:16] = final forward hidden.
// ---------------------------------------------------------------------------
__global__ void __launch_bounds__(128) gru_l1f(
    const float* __restrict__ Wih, const float* __restrict__ Whh,
    const float* __restrict__ bih, const float* __restrict__ bhh,
    float* __restrict__ out)
{
    const int tid = threadIdx.x;
    const int j = tid & 15;
    const int e = tid >> 4;
    const int b = blockIdx.x * 8 + e;

    float wi0[32], wi1[32], wi2[32];
#pragma unroll
    for (int k = 0; k < 32; ++k) {
        wi0[k] = Wih[(j)      * 32 + k];
        wi1[k] = Wih[(j + 16) * 32 + k];
        wi2[k] = Wih[(j + 32) * 32 + k];
    }
    float wr[16], wz[16], wn[16];
#pragma unroll
    for (int k = 0; k < 16; ++k) {
        wr[k] = Whh[(j)      * 16 + k];
        wz[k] = Whh[(j + 16) * 16 + k];
        wn[k] = Whh[(j + 32) * 16 + k];
    }
    const float bir = bih[j], biz = bih[j + 16], bin_ = bih[j + 32];
    const float bhr = bhh[j], bhz = bhh[j + 16], bhn = bhh[j + 32];

    const float2* yp = (const float2*)(g_y0 + (size_t)b * 32) + j;

    float h = 0.0f;
    for (int t = 0; t < TT; ++t) {
        float2 my = yp[(size_t)t * (BB * 16)];     // coalesced 256B per warp

        float ir = bir, iz = biz, in_ = bin_;
#pragma unroll
        for (int k = 0; k < 16; ++k) {
            float vx = __shfl_sync(0xFFFFFFFFu, my.x, k, 16);
            float vy = __shfl_sync(0xFFFFFFFFu, my.y, k, 16);
            ir  = fmaf(wi0[2 * k], vx, ir);  ir  = fmaf(wi0[2 * k + 1], vy, ir);
            iz  = fmaf(wi1[2 * k], vx, iz);  iz  = fmaf(wi1[2 * k + 1], vy, iz);
            in_ = fmaf(wi2[2 * k], vx, in_); in_ = fmaf(wi2[2 * k + 1], vy, in_);
        }
        float ar = bhr, az = bhz, an = bhn;
#pragma unroll
        for (int k = 0; k < 16; ++k) {
            float hk = __shfl_sync(0xFFFFFFFFu, h, k, 16);
            ar = fmaf(wr[k], hk, ar);
            az = fmaf(wz[k], hk, az);
            an = fmaf(wn[k], hk, an);
        }
        float r = sigmoid_f(ir + ar);
        float z = sigmoid_f(iz + az);
        float n = tanh_f(fmaf(r, an, in_));
        h = n + z * (h - n);
    }
    out[b * 32 + j] = h;
}

// ---------------------------------------------------------------------------
// Kernel 3: layer 1 backward at position T-1 == ONE GRU step from h=0 on
// y0[T-1] (lax.scan reverse alignment). gh = bhh only. Writes out[b][16:32].
// ---------------------------------------------------------------------------
__global__ void __launch_bounds__(128) gru_l1b(
    const float* __restrict__ Wih,
    const float* __restrict__ bih, const float* __restrict__ bhh,
    float* __restrict__ out)
{
    const int tid = threadIdx.x;
    const int j = tid & 15;
    const int e = tid >> 4;
    const int b = blockIdx.x * 8 + e;

    float wi0[32], wi1[32], wi2[32];
#pragma unroll
    for (int k = 0; k < 32; ++k) {
        wi0[k] = Wih[(j)      * 32 + k];
        wi1[k] = Wih[(j + 16) * 32 + k];
        wi2[k] = Wih[(j + 32) * 32 + k];
    }
    const float bir = bih[j], biz = bih[j + 16], bin_ = bih[j + 32];
    const float bhr = bhh[j], bhz = bhh[j + 16], bhn = bhh[j + 32];

    const float2* yp =
        (const float2*)(g_y0 + (size_t)(TT - 1) * (BB * 32) + (size_t)b * 32) + j;
    float2 my = *yp;

    float ir = bir, iz = biz, in_ = bin_;
#pragma unroll
    for (int k = 0; k < 16; ++k) {
        float vx = __shfl_sync(0xFFFFFFFFu, my.x, k, 16);
        float vy = __shfl_sync(0xFFFFFFFFu, my.y, k, 16);
        ir  = fmaf(wi0[2 * k], vx, ir);  ir  = fmaf(wi0[2 * k + 1], vy, ir);
        iz  = fmaf(wi1[2 * k], vx, iz);  iz  = fmaf(wi1[2 * k + 1], vy, iz);
        in_ = fmaf(wi2[2 * k], vx, in_); in_ = fmaf(wi2[2 * k + 1], vy, in_);
    }
    float r = sigmoid_f(ir + bhr);
    float z = sigmoid_f(iz + bhz);
    float n = tanh_f(fmaf(r, bhn, in_));
    out[b * 32 + 16 + j] = (1.0f - z) * n;   // h0 = 0
}

// ---------------------------------------------------------------------------
// Launch. Input order per metadata: x, then (Wih, Whh, bih, bhh) for
// l0_f, l0_b, l1_f, l1_b. Output: [B, 32] fp32.
// ---------------------------------------------------------------------------
extern "C" void kernel_launch(void* const* d_in, const int* in_sizes, int n_in,
                              void* d_out, int out_size) {
    const float* x = (const float*)d_in[0];

    dim3 g1(BB / 8, 2);
    gru_l0<<<g1, 128>>>(x,
        (const float*)d_in[1],  (const float*)d_in[2],
        (const float*)d_in[3],  (const float*)d_in[4],
        (const float*)d_in[5],  (const float*)d_in[6],
        (const float*)d_in[7],  (const float*)d_in[8]);

    gru_l1f<<<BB / 8, 128>>>(
        (const float*)d_in[9],  (const float*)d_in[10],
        (const float*)d_in[11], (const float*)d_in[12],
        (float*)d_out);

    gru_l1b<<<BB / 8, 128>>>(
        (const float*)d_in[13],
        (const float*)d_in[15], (const float*)d_in[16],
        (float*)d_out);
}

// round 3
// speedup vs baseline: 1.3480x; 1.3480x over previous
#include <cuda_runtime.h>

#define TT 512
#define BB 4096
#define HH 16

// Scratch (allocation APIs forbidden; __device__ globals are the sanctioned path).
// y0 = concat(layer0 fwd, layer0 bwd), [T][B][32] fp32 (268 MB).
__device__ float g_y0[(size_t)TT * BB * 32];
// gi = bih_l1f + Wih_l1f @ y0, [T][B][48] fp32 (402 MB).
__device__ float g_gi[(size_t)TT * BB * 48];

__device__ __forceinline__ float sigmoid_f(float x) {
    return __fdividef(1.0f, 1.0f + __expf(-x));
}

__device__ __forceinline__ float tanh_f(float x) {
    x = fminf(fmaxf(x, -15.0f), 15.0f);
    float e = __expf(-2.0f * x);
    return __fdividef(1.0f - e, 1.0f + e);
}

// ---------------------------------------------------------------------------
// Kernel 1: layer 0, both directions (blockIdx.y selects direction).
// 16 threads per element; thread j owns hidden unit j. h exchanged by shuffle.
// ---------------------------------------------------------------------------
__global__ void __launch_bounds__(128) gru_l0(
    const float* __restrict__ x,
    const float* __restrict__ WihF, const float* __restrict__ WhhF,
    const float* __restrict__ bihF, const float* __restrict__ bhhF,
    const float* __restrict__ WihB, const float* __restrict__ WhhB,
    const float* __restrict__ bihB, const float* __restrict__ bhhB)
{
    const int tid = threadIdx.x;
    const int j = tid & 15;
    const int e = tid >> 4;
    const int b = blockIdx.x * 8 + e;
    const bool bwd = (blockIdx.y != 0);

    const float* Wih = bwd ? WihB : WihF;
    const float* Whh = bwd ? WhhB : WhhF;
    const float* bih = bwd ? bihB : bihF;
    const float* bhh = bwd ? bhhB : bhhF;

    float wr[16], wz[16], wn[16];
#pragma unroll
    for (int k = 0; k < 16; ++k) {
        wr[k] = Whh[(j)      * 16 + k];
        wz[k] = Whh[(j + 16) * 16 + k];
        wn[k] = Whh[(j + 32) * 16 + k];
    }
    const float wir = Wih[j], wiz = Wih[j + 16], win = Wih[j + 32];
    const float bir = bih[j], biz = bih[j + 16], bin_ = bih[j + 32];
    const float bhr = bhh[j], bhz = bhh[j + 16], bhn = bhh[j + 32];

    const float* xp = x + (size_t)b * TT;          // x is [B, T, 1]
    float* yp = g_y0 + (size_t)b * 32 + (bwd ? 16 : 0) + j;

    const int t0 = bwd ? TT - 1 : 0;
    const int dt = bwd ? -1 : 1;

    float h = 0.0f;
    float xv = xp[t0];
    int t = t0;
    for (int s = 0; s < TT; ++s) {
        float xnext = (s + 1 < TT) ? xp[t + dt] : 0.0f;

        float ar = bhr, az = bhz, an = bhn;
#pragma unroll
        for (int k = 0; k < 16; ++k) {
            float hk = __shfl_sync(0xFFFFFFFFu, h, k, 16);
            ar = fmaf(wr[k], hk, ar);
            az = fmaf(wz[k], hk, az);
            an = fmaf(wn[k], hk, an);
        }
        float r = sigmoid_f(fmaf(xv, wir, bir) + ar);
        float z = sigmoid_f(fmaf(xv, wiz, biz) + az);
        float n = tanh_f(fmaf(r, an, fmaf(xv, win, bin_)));
        h = n + z * (h - n);

        yp[(size_t)t * (BB * 32)] = h;
        xv = xnext;
        t += dt;
    }
}

// ---------------------------------------------------------------------------
// Kernel 2: layer-1 forward input projection, TIME-PARALLEL (no recurrence).
// gi[t][b][48] = bih + Wih_l1f @ y0[t][b][:].
// 16 lanes per element; lane j computes gate rows {j, j+16, j+32} with the
// 96 weights in registers. y0 row (128B) read as 8 LDG.128 per lane group.
// Grid: (B/8, T/32). ~32K warps -> FMA-issue / DRAM bound.
// ---------------------------------------------------------------------------
__global__ void __launch_bounds__(128) l1_proj(
    const float* __restrict__ Wih, const float* __restrict__ bih)
{
    const int tid = threadIdx.x;
    const int j = tid & 15;
    const int e = tid >> 4;
    const int b = blockIdx.x * 8 + e;
    const int t0 = blockIdx.y * 32;

    // rows j, j+16, j+32 of Wih [48 x 32], as float4 (row = 8 float4)
    const float4* W4 = (const float4*)Wih;
    float4 w0[8], w1[8], w2[8];
#pragma unroll
    for (int q = 0; q < 8; ++q) {
        w0[q] = W4[(j)      * 8 + q];
        w1[q] = W4[(j + 16) * 8 + q];
        w2[q] = W4[(j + 32) * 8 + q];
    }
    const float b0 = bih[j], b1 = bih[j + 16], b2 = bih[j + 32];

#pragma unroll 2
    for (int t = t0; t < t0 + 32; ++t) {
        const float4* yv = (const float4*)(g_y0 + ((size_t)t * BB + b) * 32);
        float a0 = b0, a1 = b1, a2 = b2;
#pragma unroll
        for (int q = 0; q < 8; ++q) {
            float4 v = yv[q];
            a0 = fmaf(w0[q].x, v.x, a0); a0 = fmaf(w0[q].y, v.y, a0);
            a0 = fmaf(w0[q].z, v.z, a0); a0 = fmaf(w0[q].w, v.w, a0);
            a1 = fmaf(w1[q].x, v.x, a1); a1 = fmaf(w1[q].y, v.y, a1);
            a1 = fmaf(w1[q].z, v.z, a1); a1 = fmaf(w1[q].w, v.w, a1);
            a2 = fmaf(w2[q].x, v.x, a2); a2 = fmaf(w2[q].y, v.y, a2);
            a2 = fmaf(w2[q].z, v.z, a2); a2 = fmaf(w2[q].w, v.w, a2);
        }
        float* gp = g_gi + ((size_t)t * BB + b) * 48;
        gp[j]      = a0;
        gp[j + 16] = a1;
        gp[j + 32] = a2;
    }
}

// ---------------------------------------------------------------------------
// Kernel 3: layer-1 forward recurrence, consuming precomputed gi.
// Only 48 FFMA + 16 SHFL + activations per step; gi double-buffered
// (prefetch t+1 before computing t) so DRAM latency is off the serial path.
// ---------------------------------------------------------------------------
__global__ void __launch_bounds__(128) gru_l1f(
    const float* __restrict__ Whh, const float* __restrict__ bhh,
    float* __restrict__ out)
{
    const int tid = threadIdx.x;
    const int j = tid & 15;
    const int e = tid >> 4;
    const int b = blockIdx.x * 8 + e;

    float wr[16], wz[16], wn[16];
#pragma unroll
    for (int k = 0; k < 16; ++k) {
        wr[k] = Whh[(j)      * 16 + k];
        wz[k] = Whh[(j + 16) * 16 + k];
        wn[k] = Whh[(j + 32) * 16 + k];
    }
    const float bhr = bhh[j], bhz = bhh[j + 16], bhn = bhh[j + 32];

    const float* gp = g_gi + (size_t)b * 48;
    const size_t tstride = (size_t)BB * 48;

    float gr = gp[j], gz = gp[j + 16], gn = gp[j + 32];
    float h = 0.0f;
    for (int t = 0; t < TT; ++t) {
        float gr2 = 0.0f, gz2 = 0.0f, gn2 = 0.0f;
        if (t + 1 < TT) {
            const float* gq = gp + (size_t)(t + 1) * tstride;
            gr2 = gq[j]; gz2 = gq[j + 16]; gn2 = gq[j + 32];
        }

        float ar = bhr, az = bhz, an = bhn;
#pragma unroll
        for (int k = 0; k < 16; ++k) {
            float hk = __shfl_sync(0xFFFFFFFFu, h, k, 16);
            ar = fmaf(wr[k], hk, ar);
            az = fmaf(wz[k], hk, az);
            an = fmaf(wn[k], hk, an);
        }
        float r = sigmoid_f(gr + ar);
        float z = sigmoid_f(gz + az);
        float n = tanh_f(fmaf(r, an, gn));
        h = n + z * (h - n);

        gr = gr2; gz = gz2; gn = gn2;
    }
    out[b * 32 + j] = h;
}

// ---------------------------------------------------------------------------
// Kernel 4: layer-1 backward at position T-1 == one GRU step from h=0 on
// y0[T-1] (lax.scan reverse alignment). Uses its own Wih_l1_b.
// ---------------------------------------------------------------------------
__global__ void __launch_bounds__(128) gru_l1b(
    const float* __restrict__ Wih,
    const float* __restrict__ bih, const float* __restrict__ bhh,
    float* __restrict__ out)
{
    const int tid = threadIdx.x;
    const int j = tid & 15;
    const int e = tid >> 4;
    const int b = blockIdx.x * 8 + e;

    float wi0[32], wi1[32], wi2[32];
#pragma unroll
    for (int k = 0; k < 32; ++k) {
        wi0[k] = Wih[(j)      * 32 + k];
        wi1[k] = Wih[(j + 16) * 32 + k];
        wi2[k] = Wih[(j + 32) * 32 + k];
    }
    const float bir = bih[j], biz = bih[j + 16], bin_ = bih[j + 32];
    const float bhr = bhh[j], bhz = bhh[j + 16], bhn = bhh[j + 32];

    const float2* yp =
        (const float2*)(g_y0 + (size_t)(TT - 1) * (BB * 32) + (size_t)b * 32) + j;
    float2 my = *yp;

    float ir = bir, iz = biz, in_ = bin_;
#pragma unroll
    for (int k = 0; k < 16; ++k) {
        float vx = __shfl_sync(0xFFFFFFFFu, my.x, k, 16);
        float vy = __shfl_sync(0xFFFFFFFFu, my.y, k, 16);
        ir  = fmaf(wi0[2 * k], vx, ir);  ir  = fmaf(wi0[2 * k + 1], vy, ir);
        iz  = fmaf(wi1[2 * k], vx, iz);  iz  = fmaf(wi1[2 * k + 1], vy, iz);
        in_ = fmaf(wi2[2 * k], vx, in_); in_ = fmaf(wi2[2 * k + 1], vy, in_);
    }
    float r = sigmoid_f(ir + bhr);
    float z = sigmoid_f(iz + bhz);
    float n = tanh_f(fmaf(r, bhn, in_));
    out[b * 32 + 16 + j] = (1.0f - z) * n;   // h0 = 0
}

// ---------------------------------------------------------------------------
// Launch. Inputs: x, then (Wih, Whh, bih, bhh) for l0_f, l0_b, l1_f, l1_b.
// Output: [B, 32] fp32.
// ---------------------------------------------------------------------------
extern "C" void kernel_launch(void* const* d_in, const int* in_sizes, int n_in,
                              void* d_out, int out_size) {
    const float* x = (const float*)d_in[0];

    dim3 g1(BB / 8, 2);
    gru_l0<<<g1, 128>>>(x,
        (const float*)d_in[1],  (const float*)d_in[2],
        (const float*)d_in[3],  (const float*)d_in[4],
        (const float*)d_in[5],  (const float*)d_in[6],
        (const float*)d_in[7],  (const float*)d_in[8]);

    dim3 g2(BB / 8, TT / 32);
    l1_proj<<<g2, 128>>>(
        (const float*)d_in[9],  (const float*)d_in[11]);

    gru_l1f<<<BB / 8, 128>>>(
        (const float*)d_in[10], (const float*)d_in[12],
        (float*)d_out);

    gru_l1b<<<BB / 8, 128>>>(
        (const float*)d_in[13],
        (const float*)d_in[15], (const float*)d_in[16],
        (float*)d_out);
}

// round 4
// speedup vs baseline: 1.3939x; 1.0341x over previous
#include <cuda_runtime.h>

#define TT 512
#define BB 4096
#define HH 16

// Scratch (allocation APIs forbidden; __device__ globals are the sanctioned path).
// y0 = concat(layer0 fwd, layer0 bwd), [T][B][32] fp32 (268 MB).
__device__ float g_y0[(size_t)TT * BB * 32];
// gi = bih_l1f + Wih_l1f @ y0, packed [T][B][16][4] float (gr,gz,gn,pad) = 536 MB.
__device__ float4 g_gi[(size_t)TT * BB * 16];

__device__ __forceinline__ float sigmoid_f(float x) {
    return __fdividef(1.0f, 1.0f + __expf(-x));
}

__device__ __forceinline__ float tanh_f(float x) {
    x = fminf(fmaxf(x, -15.0f), 15.0f);
    float e = __expf(-2.0f * x);
    return __fdividef(1.0f - e, 1.0f + e);
}

// ---------------------------------------------------------------------------
// Kernel 1: layer 0, both directions (blockIdx.y selects direction).
// 16 threads per element; thread j owns hidden unit j. h exchanged by shuffle.
// Accumulator chains split 2x8 to shorten the serial dependency depth.
// ---------------------------------------------------------------------------
__global__ void __launch_bounds__(128) gru_l0(
    const float* __restrict__ x,
    const float* __restrict__ WihF, const float* __restrict__ WhhF,
    const float* __restrict__ bihF, const float* __restrict__ bhhF,
    const float* __restrict__ WihB, const float* __restrict__ WhhB,
    const float* __restrict__ bihB, const float* __restrict__ bhhB)
{
    const int tid = threadIdx.x;
    const int j = tid & 15;
    const int e = tid >> 4;
    const int b = blockIdx.x * 8 + e;
    const bool bwd = (blockIdx.y != 0);

    const float* Wih = bwd ? WihB : WihF;
    const float* Whh = bwd ? WhhB : WhhF;
    const float* bih = bwd ? bihB : bihF;
    const float* bhh = bwd ? bhhB : bhhF;

    float wr[16], wz[16], wn[16];
#pragma unroll
    for (int k = 0; k < 16; ++k) {
        wr[k] = Whh[(j)      * 16 + k];
        wz[k] = Whh[(j + 16) * 16 + k];
        wn[k] = Whh[(j + 32) * 16 + k];
    }
    const float wir = Wih[j], wiz = Wih[j + 16], win = Wih[j + 32];
    const float bir = bih[j], biz = bih[j + 16], bin_ = bih[j + 32];
    const float bhr = bhh[j], bhz = bhh[j + 16], bhn = bhh[j + 32];

    const float* xp = x + (size_t)b * TT;          // x is [B, T, 1]
    float* yp = g_y0 + (size_t)b * 32 + (bwd ? 16 : 0) + j;

    const int t0 = bwd ? TT - 1 : 0;
    const int dt = bwd ? -1 : 1;

    float h = 0.0f;
    float xv = xp[t0];
    int t = t0;
    for (int s = 0; s < TT; ++s) {
        float xnext = (s + 1 < TT) ? xp[t + dt] : 0.0f;

        float arA = bhr, azA = bhz, anA = bhn;
        float arB = 0.f, azB = 0.f, anB = 0.f;
#pragma unroll
        for (int k = 0; k < 8; ++k) {
            float hk = __shfl_sync(0xFFFFFFFFu, h, k, 16);
            arA = fmaf(wr[k], hk, arA);
            azA = fmaf(wz[k], hk, azA);
            anA = fmaf(wn[k], hk, anA);
        }
#pragma unroll
        for (int k = 8; k < 16; ++k) {
            float hk = __shfl_sync(0xFFFFFFFFu, h, k, 16);
            arB = fmaf(wr[k], hk, arB);
            azB = fmaf(wz[k], hk, azB);
            anB = fmaf(wn[k], hk, anB);
        }
        float ar = arA + arB, az = azA + azB, an = anA + anB;

        float r = sigmoid_f(fmaf(xv, wir, bir) + ar);
        float z = sigmoid_f(fmaf(xv, wiz, biz) + az);
        float n = tanh_f(fmaf(r, an, fmaf(xv, win, bin_)));
        h = n + z * (h - n);

        yp[(size_t)t * (BB * 32)] = h;
        xv = xnext;
        t += dt;
    }
}

// ---------------------------------------------------------------------------
// Kernel 2: layer-1 forward input projection, TIME-PARALLEL.
// gi[t][b][j] = {bih + Wih_l1f @ y0}[rows j, j+16, j+32], packed float4.
// Single STG.128 per lane per t; y0 row read as broadcast LDG.128s.
// ---------------------------------------------------------------------------
__global__ void __launch_bounds__(128) l1_proj(
    const float* __restrict__ Wih, const float* __restrict__ bih)
{
    const int tid = threadIdx.x;
    const int j = tid & 15;
    const int e = tid >> 4;
    const int b = blockIdx.x * 8 + e;
    const int t0 = blockIdx.y * 32;

    // rows j, j+16, j+32 of Wih [48 x 32], as float4 (row = 8 float4)
    const float4* W4 = (const float4*)Wih;
    float4 w0[8], w1[8], w2[8];
#pragma unroll
    for (int q = 0; q < 8; ++q) {
        w0[q] = W4[(j)      * 8 + q];
        w1[q] = W4[(j + 16) * 8 + q];
        w2[q] = W4[(j + 32) * 8 + q];
    }
    const float b0 = bih[j], b1 = bih[j + 16], b2 = bih[j + 32];

#pragma unroll 2
    for (int t = t0; t < t0 + 32; ++t) {
        const float4* yv = (const float4*)(g_y0 + ((size_t)t * BB + b) * 32);
        float a0 = b0, a1 = b1, a2 = b2;
#pragma unroll
        for (int q = 0; q < 8; ++q) {
            float4 v = yv[q];
            a0 = fmaf(w0[q].x, v.x, a0); a0 = fmaf(w0[q].y, v.y, a0);
            a0 = fmaf(w0[q].z, v.z, a0); a0 = fmaf(w0[q].w, v.w, a0);
            a1 = fmaf(w1[q].x, v.x, a1); a1 = fmaf(w1[q].y, v.y, a1);
            a1 = fmaf(w1[q].z, v.z, a1); a1 = fmaf(w1[q].w, v.w, a1);
            a2 = fmaf(w2[q].x, v.x, a2); a2 = fmaf(w2[q].y, v.y, a2);
            a2 = fmaf(w2[q].z, v.z, a2); a2 = fmaf(w2[q].w, v.w, a2);
        }
        float4 o; o.x = a0; o.y = a1; o.z = a2; o.w = 0.0f;
        g_gi[((size_t)t * BB + b) * 16 + j] = o;
    }
}

// ---------------------------------------------------------------------------
// Kernel 3: layer-1 forward recurrence, consuming packed gi.
// DEPTH-4 register shift-ring prefetch: load t+4 while computing t, giving
// ~4 steps (>1000 cyc) of slack to cover DRAM latency. One LDG.128 per step.
// ---------------------------------------------------------------------------
__global__ void __launch_bounds__(128) gru_l1f(
    const float* __restrict__ Whh, const float* __restrict__ bhh,
    float* __restrict__ out)
{
    const int tid = threadIdx.x;
    const int j = tid & 15;
    const int e = tid >> 4;
    const int b = blockIdx.x * 8 + e;

    float wr[16], wz[16], wn[16];
#pragma unroll
    for (int k = 0; k < 16; ++k) {
        wr[k] = Whh[(j)      * 16 + k];
        wz[k] = Whh[(j + 16) * 16 + k];
        wn[k] = Whh[(j + 32) * 16 + k];
    }
    const float bhr = bhh[j], bhz = bhh[j + 16], bhn = bhh[j + 32];

    const size_t ts = (size_t)BB * 16;                 // float4 stride per t
    const float4* gp = g_gi + (size_t)b * 16 + j;

    float4 p0 = gp[0 * ts];
    float4 p1 = gp[1 * ts];
    float4 p2 = gp[2 * ts];
    float4 p3 = gp[3 * ts];

    float h = 0.0f;
#pragma unroll 4
    for (int t = 0; t < TT; ++t) {
        float4 cur = p0;
        p0 = p1; p1 = p2; p2 = p3;
        if (t + 4 < TT) p3 = gp[(size_t)(t + 4) * ts];

        float arA = bhr, azA = bhz, anA = bhn;
        float arB = 0.f, azB = 0.f, anB = 0.f;
#pragma unroll
        for (int k = 0; k < 8; ++k) {
            float hk = __shfl_sync(0xFFFFFFFFu, h, k, 16);
            arA = fmaf(wr[k], hk, arA);
            azA = fmaf(wz[k], hk, azA);
            anA = fmaf(wn[k], hk, anA);
        }
#pragma unroll
        for (int k = 8; k < 16; ++k) {
            float hk = __shfl_sync(0xFFFFFFFFu, h, k, 16);
            arB = fmaf(wr[k], hk, arB);
            azB = fmaf(wz[k], hk, azB);
            anB = fmaf(wn[k], hk, anB);
        }
        float r = sigmoid_f(cur.x + arA + arB);
        float z = sigmoid_f(cur.y + azA + azB);
        float n = tanh_f(fmaf(r, anA + anB, cur.z));
        h = n + z * (h - n);
    }
    out[b * 32 + j] = h;
}

// ---------------------------------------------------------------------------
// Kernel 4: layer-1 backward at position T-1 == one GRU step from h=0 on
// y0[T-1] (lax.scan reverse alignment). Uses its own Wih_l1_b.
// ---------------------------------------------------------------------------
__global__ void __launch_bounds__(128) gru_l1b(
    const float* __restrict__ Wih,
    const float* __restrict__ bih, const float* __restrict__ bhh,
    float* __restrict__ out)
{
    const int tid = threadIdx.x;
    const int j = tid & 15;
    const int e = tid >> 4;
    const int b = blockIdx.x * 8 + e;

    float wi0[32], wi1[32], wi2[32];
#pragma unroll
    for (int k = 0; k < 32; ++k) {
        wi0[k] = Wih[(j)      * 32 + k];
        wi1[k] = Wih[(j + 16) * 32 + k];
        wi2[k] = Wih[(j + 32) * 32 + k];
    }
    const float bir = bih[j], biz = bih[j + 16], bin_ = bih[j + 32];
    const float bhr = bhh[j], bhz = bhh[j + 16], bhn = bhh[j + 32];

    const float2* yp =
        (const float2*)(g_y0 + (size_t)(TT - 1) * (BB * 32) + (size_t)b * 32) + j;
    float2 my = *yp;

    float ir = bir, iz = biz, in_ = bin_;
#pragma unroll
    for (int k = 0; k < 16; ++k) {
        float vx = __shfl_sync(0xFFFFFFFFu, my.x, k, 16);
        float vy = __shfl_sync(0xFFFFFFFFu, my.y, k, 16);
        ir  = fmaf(wi0[2 * k], vx, ir);  ir  = fmaf(wi0[2 * k + 1], vy, ir);
        iz  = fmaf(wi1[2 * k], vx, iz);  iz  = fmaf(wi1[2 * k + 1], vy, iz);
        in_ = fmaf(wi2[2 * k], vx, in_); in_ = fmaf(wi2[2 * k + 1], vy, in_);
    }
    float r = sigmoid_f(ir + bhr);
    float z = sigmoid_f(iz + bhz);
    float n = tanh_f(fmaf(r, bhn, in_));
    out[b * 32 + 16 + j] = (1.0f - z) * n;   // h0 = 0
}

// ---------------------------------------------------------------------------
// Launch. Inputs: x, then (Wih, Whh, bih, bhh) for l0_f, l0_b, l1_f, l1_b.
// Output: [B, 32] fp32.
// ---------------------------------------------------------------------------
extern "C" void kernel_launch(void* const* d_in, const int* in_sizes, int n_in,
                              void* d_out, int out_size) {
    const float* x = (const float*)d_in[0];

    dim3 g1(BB / 8, 2);
    gru_l0<<<g1, 128>>>(x,
        (const float*)d_in[1],  (const float*)d_in[2],
        (const float*)d_in[3],  (const float*)d_in[4],
        (const float*)d_in[5],  (const float*)d_in[6],
        (const float*)d_in[7],  (const float*)d_in[8]);

    dim3 g2(BB / 8, TT / 32);
    l1_proj<<<g2, 128>>>(
        (const float*)d_in[9],  (const float*)d_in[11]);

    gru_l1f<<<BB / 8, 128>>>(
        (const float*)d_in[10], (const float*)d_in[12],
        (float*)d_out);

    gru_l1b<<<BB / 8, 128>>>(
        (const float*)d_in[13],
        (const float*)d_in[15], (const float*)d_in[16],
        (float*)d_out);
}

// round 5
// speedup vs baseline: 1.4493x; 1.0397x over previous
#include <cuda_runtime.h>

#define TT 512
#define BB 4096

// Scratch (allocation APIs forbidden; __device__ globals are the sanctioned path).
__device__ float g_y0[(size_t)TT * BB * 32];            // [T][B][32] fp32, 268 MB
__device__ float4 g_gi[(size_t)TT * BB * 16];           // [T][B][16] float4 (r,z,n,pad), 536 MB

typedef unsigned long long u64;

// ---- packed f32x2 helpers (Blackwell-only; ptxas won't auto-fuse) ----
__device__ __forceinline__ u64 pack2(float lo, float hi) {
    u64 r; asm("mov.b64 %0, {%1, %2};" : "=l"(r) : "f"(lo), "f"(hi)); return r;
}
__device__ __forceinline__ void unpack2(u64 v, float& lo, float& hi) {
    asm("mov.b64 {%0, %1}, %2;" : "=f"(lo), "=f"(hi) : "l"(v));
}
__device__ __forceinline__ u64 fma2(u64 a, u64 b, u64 c) {
    u64 d; asm("fma.rn.f32x2 %0, %1, %2, %3;" : "=l"(d) : "l"(a), "l"(b), "l"(c)); return d;
}
__device__ __forceinline__ u64 add2(u64 a, u64 b) {
    u64 d; asm("add.rn.f32x2 %0, %1, %2;" : "=l"(d) : "l"(a), "l"(b)); return d;
}

__device__ __forceinline__ float sigmoid_f(float x) {
    return __fdividef(1.0f, 1.0f + __expf(-x));
}
__device__ __forceinline__ float tanh_f(float x) {
    x = fminf(fmaxf(x, -15.0f), 15.0f);
    float e = __expf(-2.0f * x);
    return __fdividef(1.0f - e, 1.0f + e);
}

// ---------------------------------------------------------------------------
// Kernel 1: layer 0, both directions (blockIdx.y). Two batch elements packed
// per lane (f32x2): 16-lane group handles elements (2P, 2P+1); the 48-FFMA
// hidden matvec runs as 48 FFMA2 serving 4 elements per warp.
// ---------------------------------------------------------------------------
__global__ void __launch_bounds__(128) gru_l0(
    const float* __restrict__ x,
    const float* __restrict__ WihF, const float* __restrict__ WhhF,
    const float* __restrict__ bihF, const float* __restrict__ bhhF,
    const float* __restrict__ WihB, const float* __restrict__ WhhB,
    const float* __restrict__ bihB, const float* __restrict__ bhhB)
{
    const int tid = threadIdx.x;
    const int j = tid & 15;
    const int P = blockIdx.x * 8 + (tid >> 4);   // element-pair index
    const int b0 = 2 * P;
    const bool bwd = (blockIdx.y != 0);

    const float* Wih = bwd ? WihB : WihF;
    const float* Whh = bwd ? WhhB : WhhF;
    const float* bih = bwd ? bihB : bihF;
    const float* bhh = bwd ? bhhB : bhhF;

    u64 wr2[16], wz2[16], wn2[16];
#pragma unroll
    for (int k = 0; k < 16; ++k) {
        float a = Whh[(j)      * 16 + k];
        float b = Whh[(j + 16) * 16 + k];
        float c = Whh[(j + 32) * 16 + k];
        wr2[k] = pack2(a, a);
        wz2[k] = pack2(b, b);
        wn2[k] = pack2(c, c);
    }
    const u64 wir2 = pack2(Wih[j], Wih[j]);
    const u64 wiz2 = pack2(Wih[j + 16], Wih[j + 16]);
    const u64 win2 = pack2(Wih[j + 32], Wih[j + 32]);
    const u64 bir2 = pack2(bih[j], bih[j]);
    const u64 biz2 = pack2(bih[j + 16], bih[j + 16]);
    const u64 bin2 = pack2(bih[j + 32], bih[j + 32]);
    const u64 bhr2 = pack2(bhh[j], bhh[j]);
    const u64 bhz2 = pack2(bhh[j + 16], bhh[j + 16]);
    const u64 bhn2 = pack2(bhh[j + 32], bhh[j + 32]);
    const u64 zero2 = 0ull;

    const float* xp0 = x + (size_t)b0 * TT;         // x is [B, T, 1]
    const float* xp1 = xp0 + TT;
    float* yp0 = g_y0 + (size_t)b0 * 32 + (bwd ? 16 : 0) + j;
    float* yp1 = yp0 + 32;

    const int t0 = bwd ? TT - 1 : 0;
    const int dt = bwd ? -1 : 1;

    u64 h2 = 0ull;
    u64 xv2 = pack2(xp0[t0], xp1[t0]);
    int t = t0;
    for (int s = 0; s < TT; ++s) {
        u64 xnext = 0ull;
        if (s + 1 < TT) xnext = pack2(xp0[t + dt], xp1[t + dt]);

        u64 arA = bhr2, azA = bhz2, anA = bhn2;
        u64 arB = zero2, azB = zero2, anB = zero2;
#pragma unroll
        for (int k = 0; k < 8; ++k) {
            u64 hk = __shfl_sync(0xFFFFFFFFu, h2, k, 16);
            arA = fma2(wr2[k], hk, arA);
            azA = fma2(wz2[k], hk, azA);
            anA = fma2(wn2[k], hk, anA);
        }
#pragma unroll
        for (int k = 8; k < 16; ++k) {
            u64 hk = __shfl_sync(0xFFFFFFFFu, h2, k, 16);
            arB = fma2(wr2[k], hk, arB);
            azB = fma2(wz2[k], hk, azB);
            anB = fma2(wn2[k], hk, anB);
        }
        u64 ar = add2(arA, arB);
        u64 az = add2(azA, azB);
        u64 an = add2(anA, anB);

        u64 pr = add2(fma2(xv2, wir2, bir2), ar);    // pre-act r (2 elems)
        u64 pz = add2(fma2(xv2, wiz2, biz2), az);
        float prx, pry, pzx, pzy;
        unpack2(pr, prx, pry);
        unpack2(pz, pzx, pzy);
        float r0 = sigmoid_f(prx), r1 = sigmoid_f(pry);
        float z0 = sigmoid_f(pzx), z1 = sigmoid_f(pzy);

        u64 pn = fma2(pack2(r0, r1), an, fma2(xv2, win2, bin2));
        float pnx, pny;
        unpack2(pn, pnx, pny);
        float n0 = tanh_f(pnx), n1 = tanh_f(pny);

        float h0, h1;
        unpack2(h2, h0, h1);
        h0 = n0 + z0 * (h0 - n0);
        h1 = n1 + z1 * (h1 - n1);
        h2 = pack2(h0, h1);

        yp0[(size_t)t * (BB * 32)] = h0;
        yp1[(size_t)t * (BB * 32)] = h1;
        xv2 = xnext;
        t += dt;
    }
}

// ---------------------------------------------------------------------------
// Kernel 2: layer-1 forward input projection, TIME-PARALLEL (unchanged).
// ---------------------------------------------------------------------------
__global__ void __launch_bounds__(128) l1_proj(
    const float* __restrict__ Wih, const float* __restrict__ bih)
{
    const int tid = threadIdx.x;
    const int j = tid & 15;
    const int e = tid >> 4;
    const int b = blockIdx.x * 8 + e;
    const int t0 = blockIdx.y * 32;

    const float4* W4 = (const float4*)Wih;
    float4 w0[8], w1[8], w2[8];
#pragma unroll
    for (int q = 0; q < 8; ++q) {
        w0[q] = W4[(j)      * 8 + q];
        w1[q] = W4[(j + 16) * 8 + q];
        w2[q] = W4[(j + 32) * 8 + q];
    }
    const float b0 = bih[j], b1 = bih[j + 16], b2 = bih[j + 32];

#pragma unroll 2
    for (int t = t0; t < t0 + 32; ++t) {
        const float4* yv = (const float4*)(g_y0 + ((size_t)t * BB + b) * 32);
        float a0 = b0, a1 = b1, a2 = b2;
#pragma unroll
        for (int q = 0; q < 8; ++q) {
            float4 v = yv[q];
            a0 = fmaf(w0[q].x, v.x, a0); a0 = fmaf(w0[q].y, v.y, a0);
            a0 = fmaf(w0[q].z, v.z, a0); a0 = fmaf(w0[q].w, v.w, a0);
            a1 = fmaf(w1[q].x, v.x, a1); a1 = fmaf(w1[q].y, v.y, a1);
            a1 = fmaf(w1[q].z, v.z, a1); a1 = fmaf(w1[q].w, v.w, a1);
            a2 = fmaf(w2[q].x, v.x, a2); a2 = fmaf(w2[q].y, v.y, a2);
            a2 = fmaf(w2[q].z, v.z, a2); a2 = fmaf(w2[q].w, v.w, a2);
        }
        float4 o; o.x = a0; o.y = a1; o.z = a2; o.w = 0.0f;
        g_gi[((size_t)t * BB + b) * 16 + j] = o;
    }
}

// ---------------------------------------------------------------------------
// Kernel 3: layer-1 forward recurrence, f32x2-packed (2 elements per lane),
// depth-4 ring prefetch of packed gi.
// ---------------------------------------------------------------------------
__global__ void __launch_bounds__(128) gru_l1f(
    const float* __restrict__ Whh, const float* __restrict__ bhh,
    float* __restrict__ out)
{
    const int tid = threadIdx.x;
    const int j = tid & 15;
    const int P = blockIdx.x * 8 + (tid >> 4);
    const int b0 = 2 * P;

    u64 wr2[16], wz2[16], wn2[16];
#pragma unroll
    for (int k = 0; k < 16; ++k) {
        float a = Whh[(j)      * 16 + k];
        float b = Whh[(j + 16) * 16 + k];
        float c = Whh[(j + 32) * 16 + k];
        wr2[k] = pack2(a, a);
        wz2[k] = pack2(b, b);
        wn2[k] = pack2(c, c);
    }
    const u64 bhr2 = pack2(bhh[j], bhh[j]);
    const u64 bhz2 = pack2(bhh[j + 16], bhh[j + 16]);
    const u64 bhn2 = pack2(bhh[j + 32], bhh[j + 32]);
    const u64 zero2 = 0ull;

    const size_t ts = (size_t)BB * 16;                 // float4 stride per t
    const float4* gp0 = g_gi + (size_t)b0 * 16 + j;
    const float4* gp1 = gp0 + 16;

    u64 rr[4], rz[4], rn[4];
#pragma unroll
    for (int q = 0; q < 4; ++q) {
        float4 A = gp0[(size_t)q * ts];
        float4 B = gp1[(size_t)q * ts];
        rr[q] = pack2(A.x, B.x);
        rz[q] = pack2(A.y, B.y);
        rn[q] = pack2(A.z, B.z);
    }

    u64 h2 = 0ull;
#pragma unroll 4
    for (int t = 0; t < TT; ++t) {
        const int sl = t & 3;
        u64 gr2 = rr[sl], gz2 = rz[sl], gn2 = rn[sl];
        if (t + 4 < TT) {
            float4 A = gp0[(size_t)(t + 4) * ts];
            float4 B = gp1[(size_t)(t + 4) * ts];
            rr[sl] = pack2(A.x, B.x);
            rz[sl] = pack2(A.y, B.y);
            rn[sl] = pack2(A.z, B.z);
        }

        u64 arA = bhr2, azA = bhz2, anA = bhn2;
        u64 arB = zero2, azB = zero2, anB = zero2;
#pragma unroll
        for (int k = 0; k < 8; ++k) {
            u64 hk = __shfl_sync(0xFFFFFFFFu, h2, k, 16);
            arA = fma2(wr2[k], hk, arA);
            azA = fma2(wz2[k], hk, azA);
            anA = fma2(wn2[k], hk, anA);
        }
#pragma unroll
        for (int k = 8; k < 16; ++k) {
            u64 hk = __shfl_sync(0xFFFFFFFFu, h2, k, 16);
            arB = fma2(wr2[k], hk, arB);
            azB = fma2(wz2[k], hk, azB);
            anB = fma2(wn2[k], hk, anB);
        }
        u64 pr = add2(gr2, add2(arA, arB));
        u64 pz = add2(gz2, add2(azA, azB));
        u64 an = add2(anA, anB);

        float prx, pry, pzx, pzy;
        unpack2(pr, prx, pry);
        unpack2(pz, pzx, pzy);
        float r0 = sigmoid_f(prx), r1 = sigmoid_f(pry);
        float z0 = sigmoid_f(pzx), z1 = sigmoid_f(pzy);

        u64 pn = fma2(pack2(r0, r1), an, gn2);
        float pnx, pny;
        unpack2(pn, pnx, pny);
        float n0 = tanh_f(pnx), n1 = tanh_f(pny);

        float h0, h1;
        unpack2(h2, h0, h1);
        h0 = n0 + z0 * (h0 - n0);
        h1 = n1 + z1 * (h1 - n1);
        h2 = pack2(h0, h1);
    }

    float h0, h1;
    unpack2(h2, h0, h1);
    out[b0 * 32 + j] = h0;
    out[(b0 + 1) * 32 + j] = h1;
}

// ---------------------------------------------------------------------------
// Kernel 4: layer-1 backward at position T-1 == one GRU step from h=0 on
// y0[T-1] (lax.scan reverse alignment). Unchanged.
// ---------------------------------------------------------------------------
__global__ void __launch_bounds__(128) gru_l1b(
    const float* __restrict__ Wih,
    const float* __restrict__ bih, const float* __restrict__ bhh,
    float* __restrict__ out)
{
    const int tid = threadIdx.x;
    const int j = tid & 15;
    const int e = tid >> 4;
    const int b = blockIdx.x * 8 + e;

    float wi0[32], wi1[32], wi2[32];
#pragma unroll
    for (int k = 0; k < 32; ++k) {
        wi0[k] = Wih[(j)      * 32 + k];
        wi1[k] = Wih[(j + 16) * 32 + k];
        wi2[k] = Wih[(j + 32) * 32 + k];
    }
    const float bir = bih[j], biz = bih[j + 16], bin_ = bih[j + 32];
    const float bhr = bhh[j], bhz = bhh[j + 16], bhn = bhh[j + 32];

    const float2* yp =
        (const float2*)(g_y0 + (size_t)(TT - 1) * (BB * 32) + (size_t)b * 32) + j;
    float2 my = *yp;

    float ir = bir, iz = biz, in_ = bin_;
#pragma unroll
    for (int k = 0; k < 16; ++k) {
        float vx = __shfl_sync(0xFFFFFFFFu, my.x, k, 16);
        float vy = __shfl_sync(0xFFFFFFFFu, my.y, k, 16);
        ir  = fmaf(wi0[2 * k], vx, ir);  ir  = fmaf(wi0[2 * k + 1], vy, ir);
        iz  = fmaf(wi1[2 * k], vx, iz);  iz  = fmaf(wi1[2 * k + 1], vy, iz);
        in_ = fmaf(wi2[2 * k], vx, in_); in_ = fmaf(wi2[2 * k + 1], vy, in_);
    }
    float r = sigmoid_f(ir + bhr);
    float z = sigmoid_f(iz + bhz);
    float n = tanh_f(fmaf(r, bhn, in_));
    out[b * 32 + 16 + j] = (1.0f - z) * n;   // h0 = 0
}

// ---------------------------------------------------------------------------
// Launch. Inputs: x, then (Wih, Whh, bih, bhh) for l0_f, l0_b, l1_f, l1_b.
// Output: [B, 32] fp32.
// ---------------------------------------------------------------------------
extern "C" void kernel_launch(void* const* d_in, const int* in_sizes, int n_in,
                              void* d_out, int out_size) {
    const float* x = (const float*)d_in[0];

    dim3 g1(BB / 16, 2);
    gru_l0<<<g1, 128>>>(x,
        (const float*)d_in[1],  (const float*)d_in[2],
        (const float*)d_in[3],  (const float*)d_in[4],
        (const float*)d_in[5],  (const float*)d_in[6],
        (const float*)d_in[7],  (const float*)d_in[8]);

    dim3 g2(BB / 8, TT / 32);
    l1_proj<<<g2, 128>>>(
        (const float*)d_in[9],  (const float*)d_in[11]);

    gru_l1f<<<BB / 16, 128>>>(
        (const float*)d_in[10], (const float*)d_in[12],
        (float*)d_out);

    gru_l1b<<<BB / 8, 128>>>(
        (const float*)d_in[13],
        (const float*)d_in[15], (const float*)d_in[16],
        (float*)d_out);
}

// round 6
// speedup vs baseline: 1.8586x; 1.2824x over previous
#include <cuda_runtime.h>

#define TT 512
#define BB 4096

// Scratch (allocation APIs forbidden; __device__ globals are the sanctioned path).
__device__ float g_y0[(size_t)TT * BB * 32];            // [T][B][32] fp32, 268 MB
__device__ float4 g_gi[(size_t)TT * BB * 16];           // [T][B][16] float4 (r,z,n,pad), 536 MB

typedef unsigned long long u64;

// ---- packed f32x2 helpers (Blackwell-only; ptxas won't auto-fuse) ----
__device__ __forceinline__ u64 pack2(float lo, float hi) {
    u64 r; asm("mov.b64 %0, {%1, %2};" : "=l"(r) : "f"(lo), "f"(hi)); return r;
}
__device__ __forceinline__ void unpack2(u64 v, float& lo, float& hi) {
    asm("mov.b64 {%0, %1}, %2;" : "=f"(lo), "=f"(hi) : "l"(v));
}
__device__ __forceinline__ u64 fma2(u64 a, u64 b, u64 c) {
    u64 d; asm("fma.rn.f32x2 %0, %1, %2, %3;" : "=l"(d) : "l"(a), "l"(b), "l"(c)); return d;
}
__device__ __forceinline__ u64 add2(u64 a, u64 b) {
    u64 d; asm("add.rn.f32x2 %0, %1, %2;" : "=l"(d) : "l"(a), "l"(b)); return d;
}

// ---- fast activations: single-MUFU tanh (sm_75+), sigmoid via tanh identity ----
__device__ __forceinline__ float tanh_fast(float x) {
    float y; asm("tanh.approx.f32 %0, %1;" : "=f"(y) : "f"(x)); return y;
}
__device__ __forceinline__ float sigmoid_fast(float x) {
    return fmaf(tanh_fast(0.5f * x), 0.5f, 0.5f);   // 0.5*(1+tanh(x/2))
}

// ---------------------------------------------------------------------------
// Kernel 1: layer 0, both directions (blockIdx.y). Two batch elements packed
// per lane (f32x2); 16-lane group handles elements (2P, 2P+1).
// ---------------------------------------------------------------------------
__global__ void __launch_bounds__(128) gru_l0(
    const float* __restrict__ x,
    const float* __restrict__ WihF, const float* __restrict__ WhhF,
    const float* __restrict__ bihF, const float* __restrict__ bhhF,
    const float* __restrict__ WihB, const float* __restrict__ WhhB,
    const float* __restrict__ bihB, const float* __restrict__ bhhB)
{
    const int tid = threadIdx.x;
    const int j = tid & 15;
    const int P = blockIdx.x * 8 + (tid >> 4);   // element-pair index
    const int b0 = 2 * P;
    const bool bwd = (blockIdx.y != 0);

    const float* Wih = bwd ? WihB : WihF;
    const float* Whh = bwd ? WhhB : WhhF;
    const float* bih = bwd ? bihB : bihF;
    const float* bhh = bwd ? bhhB : bhhF;

    u64 wr2[16], wz2[16], wn2[16];
#pragma unroll
    for (int k = 0; k < 16; ++k) {
        float a = Whh[(j)      * 16 + k];
        float b = Whh[(j + 16) * 16 + k];
        float c = Whh[(j + 32) * 16 + k];
        wr2[k] = pack2(a, a);
        wz2[k] = pack2(b, b);
        wn2[k] = pack2(c, c);
    }
    const u64 wir2 = pack2(Wih[j], Wih[j]);
    const u64 wiz2 = pack2(Wih[j + 16], Wih[j + 16]);
    const u64 win2 = pack2(Wih[j + 32], Wih[j + 32]);
    const u64 bir2 = pack2(bih[j], bih[j]);
    const u64 biz2 = pack2(bih[j + 16], bih[j + 16]);
    const u64 bin2 = pack2(bih[j + 32], bih[j + 32]);
    const u64 bhr2 = pack2(bhh[j], bhh[j]);
    const u64 bhz2 = pack2(bhh[j + 16], bhh[j + 16]);
    const u64 bhn2 = pack2(bhh[j + 32], bhh[j + 32]);
    const u64 zero2 = 0ull;

    const int dt = bwd ? -1 : 1;
    const int t0 = bwd ? TT - 1 : 0;
    const long ystep = (long)(BB * 32) * dt;     // float stride per step

    const float* xq0 = x + (size_t)b0 * TT + t0;       // x is [B, T, 1]
    const float* xq1 = xq0 + TT;
    float* yq0 = g_y0 + (size_t)t0 * (BB * 32) + (size_t)b0 * 32 + (bwd ? 16 : 0) + j;
    float* yq1 = yq0 + 32;

    u64 h2 = 0ull;
    u64 xv2 = pack2(*xq0, *xq1);
    for (int s = 0; s < TT; ++s) {
        u64 xnext = 0ull;
        if (s + 1 < TT) xnext = pack2(xq0[dt * (s + 1)], xq1[dt * (s + 1)]);

        u64 arA = bhr2, azA = bhz2, anA = bhn2;
        u64 arB = zero2, azB = zero2, anB = zero2;
#pragma unroll
        for (int k = 0; k < 8; ++k) {
            u64 hk = __shfl_sync(0xFFFFFFFFu, h2, k, 16);
            arA = fma2(wr2[k], hk, arA);
            azA = fma2(wz2[k], hk, azA);
            anA = fma2(wn2[k], hk, anA);
        }
#pragma unroll
        for (int k = 8; k < 16; ++k) {
            u64 hk = __shfl_sync(0xFFFFFFFFu, h2, k, 16);
            arB = fma2(wr2[k], hk, arB);
            azB = fma2(wz2[k], hk, azB);
            anB = fma2(wn2[k], hk, anB);
        }
        u64 an = add2(anA, anB);

        u64 pr = add2(fma2(xv2, wir2, bir2), add2(arA, arB));
        u64 pz = add2(fma2(xv2, wiz2, biz2), add2(azA, azB));
        float prx, pry, pzx, pzy;
        unpack2(pr, prx, pry);
        unpack2(pz, pzx, pzy);
        float r0 = sigmoid_fast(prx), r1 = sigmoid_fast(pry);
        float z0 = sigmoid_fast(pzx), z1 = sigmoid_fast(pzy);

        u64 pn = fma2(pack2(r0, r1), an, fma2(xv2, win2, bin2));
        float pnx, pny;
        unpack2(pn, pnx, pny);
        float n0 = tanh_fast(pnx), n1 = tanh_fast(pny);

        float h0, h1;
        unpack2(h2, h0, h1);
        h0 = n0 + z0 * (h0 - n0);
        h1 = n1 + z1 * (h1 - n1);
        h2 = pack2(h0, h1);

        *yq0 = h0;
        *yq1 = h1;
        yq0 += ystep;
        yq1 += ystep;
        xv2 = xnext;
    }
}

// ---------------------------------------------------------------------------
// Kernel 2: layer-1 forward input projection, TIME-PARALLEL (unchanged).
// ---------------------------------------------------------------------------
__global__ void __launch_bounds__(128) l1_proj(
    const float* __restrict__ Wih, const float* __restrict__ bih)
{
    const int tid = threadIdx.x;
    const int j = tid & 15;
    const int e = tid >> 4;
    const int b = blockIdx.x * 8 + e;
    const int t0 = blockIdx.y * 32;

    const float4* W4 = (const float4*)Wih;
    float4 w0[8], w1[8], w2[8];
#pragma unroll
    for (int q = 0; q < 8; ++q) {
        w0[q] = W4[(j)      * 8 + q];
        w1[q] = W4[(j + 16) * 8 + q];
        w2[q] = W4[(j + 32) * 8 + q];
    }
    const float b0 = bih[j], b1 = bih[j + 16], b2 = bih[j + 32];

    const float4* yv = (const float4*)(g_y0 + ((size_t)t0 * BB + b) * 32);
    float4* go = g_gi + ((size_t)t0 * BB + b) * 16 + j;

#pragma unroll 2
    for (int t = 0; t < 32; ++t) {
        float a0 = b0, a1 = b1, a2 = b2;
#pragma unroll
        for (int q = 0; q < 8; ++q) {
            float4 v = yv[q];
            a0 = fmaf(w0[q].x, v.x, a0); a0 = fmaf(w0[q].y, v.y, a0);
            a0 = fmaf(w0[q].z, v.z, a0); a0 = fmaf(w0[q].w, v.w, a0);
            a1 = fmaf(w1[q].x, v.x, a1); a1 = fmaf(w1[q].y, v.y, a1);
            a1 = fmaf(w1[q].z, v.z, a1); a1 = fmaf(w1[q].w, v.w, a1);
            a2 = fmaf(w2[q].x, v.x, a2); a2 = fmaf(w2[q].y, v.y, a2);
            a2 = fmaf(w2[q].z, v.z, a2); a2 = fmaf(w2[q].w, v.w, a2);
        }
        float4 o; o.x = a0; o.y = a1; o.z = a2; o.w = 0.0f;
        *go = o;
        yv += (size_t)BB * 8;       // next t (float4 units)
        go += (size_t)BB * 16;
    }
}

// ---------------------------------------------------------------------------
// Kernel 3: layer-1 forward recurrence, f32x2-packed, depth-4 ring prefetch,
// pointer-bump addressing, fast activations.
// ---------------------------------------------------------------------------
__global__ void __launch_bounds__(128) gru_l1f(
    const float* __restrict__ Whh, const float* __restrict__ bhh,
    float* __restrict__ out)
{
    const int tid = threadIdx.x;
    const int j = tid & 15;
    const int P = blockIdx.x * 8 + (tid >> 4);
    const int b0 = 2 * P;

    u64 wr2[16], wz2[16], wn2[16];
#pragma unroll
    for (int k = 0; k < 16; ++k) {
        float a = Whh[(j)      * 16 + k];
        float b = Whh[(j + 16) * 16 + k];
        float c = Whh[(j + 32) * 16 + k];
        wr2[k] = pack2(a, a);
        wz2[k] = pack2(b, b);
        wn2[k] = pack2(c, c);
    }
    const u64 bhr2 = pack2(bhh[j], bhh[j]);
    const u64 bhz2 = pack2(bhh[j + 16], bhh[j + 16]);
    const u64 bhn2 = pack2(bhh[j + 32], bhh[j + 32]);
    const u64 zero2 = 0ull;

    const size_t ts = (size_t)BB * 16;                 // float4 stride per t
    const float4* gp0 = g_gi + (size_t)b0 * 16 + j;    // element b0
    const float4* gp1 = gp0 + 16;                      // element b0+1
    const float4* pf0 = gp0 + 4 * ts;                  // prefetch cursor (t+4)
    const float4* pf1 = pf0 + 16;

    u64 rr[4], rz[4], rn[4];
#pragma unroll
    for (int q = 0; q < 4; ++q) {
        float4 A = gp0[(size_t)q * ts];
        float4 B = gp1[(size_t)q * ts];
        rr[q] = pack2(A.x, B.x);
        rz[q] = pack2(A.y, B.y);
        rn[q] = pack2(A.z, B.z);
    }

    u64 h2 = 0ull;
#pragma unroll 4
    for (int t = 0; t < TT; ++t) {
        const int sl = t & 3;
        u64 gr2 = rr[sl], gz2 = rz[sl], gn2 = rn[sl];
        if (t + 4 < TT) {
            float4 A = *pf0;
            float4 B = *pf1;
            rr[sl] = pack2(A.x, B.x);
            rz[sl] = pack2(A.y, B.y);
            rn[sl] = pack2(A.z, B.z);
        }
        pf0 += ts; pf1 += ts;

        u64 arA = bhr2, azA = bhz2, anA = bhn2;
        u64 arB = zero2, azB = zero2, anB = zero2;
#pragma unroll
        for (int k = 0; k < 8; ++k) {
            u64 hk = __shfl_sync(0xFFFFFFFFu, h2, k, 16);
            arA = fma2(wr2[k], hk, arA);
            azA = fma2(wz2[k], hk, azA);
            anA = fma2(wn2[k], hk, anA);
        }
#pragma unroll
        for (int k = 8; k < 16; ++k) {
            u64 hk = __shfl_sync(0xFFFFFFFFu, h2, k, 16);
            arB = fma2(wr2[k], hk, arB);
            azB = fma2(wz2[k], hk, azB);
            anB = fma2(wn2[k], hk, anB);
        }
        u64 pr = add2(gr2, add2(arA, arB));
        u64 pz = add2(gz2, add2(azA, azB));
        u64 an = add2(anA, anB);

        float prx, pry, pzx, pzy;
        unpack2(pr, prx, pry);
        unpack2(pz, pzx, pzy);
        float r0 = sigmoid_fast(prx), r1 = sigmoid_fast(pry);
        float z0 = sigmoid_fast(pzx), z1 = sigmoid_fast(pzy);

        u64 pn = fma2(pack2(r0, r1), an, gn2);
        float pnx, pny;
        unpack2(pn, pnx, pny);
        float n0 = tanh_fast(pnx), n1 = tanh_fast(pny);

        float h0, h1;
        unpack2(h2, h0, h1);
        h0 = n0 + z0 * (h0 - n0);
        h1 = n1 + z1 * (h1 - n1);
        h2 = pack2(h0, h1);
    }

    float h0, h1;
    unpack2(h2, h0, h1);
    out[b0 * 32 + j] = h0;
    out[(b0 + 1) * 32 + j] = h1;
}

// ---------------------------------------------------------------------------
// Kernel 4: layer-1 backward at position T-1 == one GRU step from h=0 on
// y0[T-1] (lax.scan reverse alignment).
// ---------------------------------------------------------------------------
__global__ void __launch_bounds__(128) gru_l1b(
    const float* __restrict__ Wih,
    const float* __restrict__ bih, const float* __restrict__ bhh,
    float* __restrict__ out)
{
    const int tid = threadIdx.x;
    const int j = tid & 15;
    const int e = tid >> 4;
    const int b = blockIdx.x * 8 + e;

    float wi0[32], wi1[32], wi2[32];
#pragma unroll
    for (int k = 0; k < 32; ++k) {
        wi0[k] = Wih[(j)      * 32 + k];
        wi1[k] = Wih[(j + 16) * 32 + k];
        wi2[k] = Wih[(j + 32) * 32 + k];
    }
    const float bir = bih[j], biz = bih[j + 16], bin_ = bih[j + 32];
    const float bhr = bhh[j], bhz = bhh[j + 16], bhn = bhh[j + 32];

    const float2* yp =
        (const float2*)(g_y0 + (size_t)(TT - 1) * (BB * 32) + (size_t)b * 32) + j;
    float2 my = *yp;

    float ir = bir, iz = biz, in_ = bin_;
#pragma unroll
    for (int k = 0; k < 16; ++k) {
        float vx = __shfl_sync(0xFFFFFFFFu, my.x, k, 16);
        float vy = __shfl_sync(0xFFFFFFFFu, my.y, k, 16);
        ir  = fmaf(wi0[2 * k], vx, ir);  ir  = fmaf(wi0[2 * k + 1], vy, ir);
        iz  = fmaf(wi1[2 * k], vx, iz);  iz  = fmaf(wi1[2 * k + 1], vy, iz);
        in_ = fmaf(wi2[2 * k], vx, in_); in_ = fmaf(wi2[2 * k + 1], vy, in_);
    }
    float r = sigmoid_fast(ir + bhr);
    float z = sigmoid_fast(iz + bhz);
    float n = tanh_fast(fmaf(r, bhn, in_));
    out[b * 32 + 16 + j] = (1.0f - z) * n;   // h0 = 0
}

// ---------------------------------------------------------------------------
// Launch. Inputs: x, then (Wih, Whh, bih, bhh) for l0_f, l0_b, l1_f, l1_b.
// Order: l0, l1b, proj, l1f — dependency-safe (l1b only needs y0) and steers
// the ncu capture slot (4th launch) onto gru_l1f for attribution.
// ---------------------------------------------------------------------------
extern "C" void kernel_launch(void* const* d_in, const int* in_sizes, int n_in,
                              void* d_out, int out_size) {
    const float* x = (const float*)d_in[0];

    dim3 g1(BB / 16, 2);
    gru_l0<<<g1, 128>>>(x,
        (const float*)d_in[1],  (const float*)d_in[2],
        (const float*)d_in[3],  (const float*)d_in[4],
        (const float*)d_in[5],  (const float*)d_in[6],
        (const float*)d_in[7],  (const float*)d_in[8]);

    gru_l1b<<<BB / 8, 128>>>(
        (const float*)d_in[13],
        (const float*)d_in[15], (const float*)d_in[16],
        (float*)d_out);

    dim3 g2(BB / 8, TT / 32);
    l1_proj<<<g2, 128>>>(
        (const float*)d_in[9],  (const float*)d_in[11]);

    gru_l1f<<<BB / 16, 128>>>(
        (const float*)d_in[10], (const float*)d_in[12],
        (float*)d_out);
}

// round 7
// speedup vs baseline: 1.9188x; 1.0324x over previous
#include <cuda_runtime.h>

#define TT 512
#define BB 4096

typedef unsigned long long u64;

// Scratch (allocation APIs forbidden; __device__ globals are the sanctioned path).
// y0 pair-interleaved: [T][B/2][32] u64, each u64 = {val(b_even), val(b_odd)}.
// i index = dir*16 + j (fwd units 0..15, bwd units 16..31). 268 MB.
__device__ u64 g_y0p[(size_t)TT * (BB / 2) * 32];
// gi = bih_l1f + Wih_l1f @ y0 : [T][B][16] float4 (r,z,n,pad). 536 MB.
__device__ float4 g_gi[(size_t)TT * BB * 16];

// ---- packed f32x2 helpers (Blackwell-only; ptxas won't auto-fuse) ----
__device__ __forceinline__ u64 pack2(float lo, float hi) {
    u64 r; asm("mov.b64 %0, {%1, %2};" : "=l"(r) : "f"(lo), "f"(hi)); return r;
}
__device__ __forceinline__ void unpack2(u64 v, float& lo, float& hi) {
    asm("mov.b64 {%0, %1}, %2;" : "=f"(lo), "=f"(hi) : "l"(v));
}
__device__ __forceinline__ u64 fma2(u64 a, u64 b, u64 c) {
    u64 d; asm("fma.rn.f32x2 %0, %1, %2, %3;" : "=l"(d) : "l"(a), "l"(b), "l"(c)); return d;
}
__device__ __forceinline__ u64 add2(u64 a, u64 b) {
    u64 d; asm("add.rn.f32x2 %0, %1, %2;" : "=l"(d) : "l"(a), "l"(b)); return d;
}

// ---- fast activations: single-MUFU tanh, sigmoid via tanh identity ----
__device__ __forceinline__ float tanh_fast(float x) {
    float y; asm("tanh.approx.f32 %0, %1;" : "=f"(y) : "f"(x)); return y;
}
__device__ __forceinline__ float sigmoid_fast(float x) {
    return fmaf(tanh_fast(0.5f * x), 0.5f, 0.5f);
}

// ---------------------------------------------------------------------------
// Kernel 1: layer 0, both directions (blockIdx.y). FOUR batch elements per
// lane = two independent f32x2 chains (A, B) sharing the register-resident
// weights -> 2x ILP at the same warp supply. 64-thread blocks for spread.
// ---------------------------------------------------------------------------
__global__ void __launch_bounds__(64) gru_l0(
    const float* __restrict__ x,
    const float* __restrict__ WihF, const float* __restrict__ WhhF,
    const float* __restrict__ bihF, const float* __restrict__ bhhF,
    const float* __restrict__ WihB, const float* __restrict__ WhhB,
    const float* __restrict__ bihB, const float* __restrict__ bhhB)
{
    const int tid = threadIdx.x;
    const int j = tid & 15;
    const int g = tid >> 4;                       // group 0..3
    const int b0 = (blockIdx.x * 4 + g) * 4;      // elements b0..b0+3
    const bool bwd = (blockIdx.y != 0);

    const float* Wih = bwd ? WihB : WihF;
    const float* Whh = bwd ? WhhB : WhhF;
    const float* bih = bwd ? bihB : bihF;
    const float* bhh = bwd ? bhhB : bhhF;

    u64 wr2[16], wz2[16], wn2[16];
#pragma unroll
    for (int k = 0; k < 16; ++k) {
        float a = Whh[(j)      * 16 + k];
        float b = Whh[(j + 16) * 16 + k];
        float c = Whh[(j + 32) * 16 + k];
        wr2[k] = pack2(a, a);
        wz2[k] = pack2(b, b);
        wn2[k] = pack2(c, c);
    }
    const u64 wir2 = pack2(Wih[j], Wih[j]);
    const u64 wiz2 = pack2(Wih[j + 16], Wih[j + 16]);
    const u64 win2 = pack2(Wih[j + 32], Wih[j + 32]);
    const u64 bir2 = pack2(bih[j], bih[j]);
    const u64 biz2 = pack2(bih[j + 16], bih[j + 16]);
    const u64 bin2 = pack2(bih[j + 32], bih[j + 32]);
    const u64 bhr2 = pack2(bhh[j], bhh[j]);
    const u64 bhz2 = pack2(bhh[j + 16], bhh[j + 16]);
    const u64 bhn2 = pack2(bhh[j + 32], bhh[j + 32]);

    const int dt = bwd ? -1 : 1;
    const int t0 = bwd ? TT - 1 : 0;
    const int dir16 = bwd ? 16 : 0;

    const float* xA0 = x + (size_t)b0 * TT + t0;       // x is [B, T, 1]
    const float* xA1 = xA0 + TT;
    const float* xB0 = xA0 + 2 * TT;
    const float* xB1 = xA0 + 3 * TT;

    const long ystep = (long)((BB / 2) * 32) * dt;     // u64 units per t
    u64* yq = g_y0p + (size_t)t0 * ((BB / 2) * 32) + (size_t)(b0 >> 1) * 32 + dir16 + j;
    // pair A at yq[0], pair B at yq[32]

    u64 hA = 0ull, hB = 0ull;
    u64 xvA = pack2(*xA0, *xA1);
    u64 xvB = pack2(*xB0, *xB1);

    for (int s = 0; s < TT; ++s) {
        u64 xnA = 0ull, xnB = 0ull;
        if (s + 1 < TT) {
            const int off = dt * (s + 1);
            xnA = pack2(xA0[off], xA1[off]);
            xnB = pack2(xB0[off], xB1[off]);
        }

        u64 arA = bhr2, azA = bhz2, anA = bhn2;
        u64 arB = bhr2, azB = bhz2, anB = bhn2;
#pragma unroll
        for (int k = 0; k < 16; ++k) {
            u64 hkA = __shfl_sync(0xFFFFFFFFu, hA, k, 16);
            u64 hkB = __shfl_sync(0xFFFFFFFFu, hB, k, 16);
            arA = fma2(wr2[k], hkA, arA);
            arB = fma2(wr2[k], hkB, arB);
            azA = fma2(wz2[k], hkA, azA);
            azB = fma2(wz2[k], hkB, azB);
            anA = fma2(wn2[k], hkA, anA);
            anB = fma2(wn2[k], hkB, anB);
        }

        // pair A gates
        u64 prA = add2(fma2(xvA, wir2, bir2), arA);
        u64 pzA = add2(fma2(xvA, wiz2, biz2), azA);
        float prx, pry, pzx, pzy;
        unpack2(prA, prx, pry);
        unpack2(pzA, pzx, pzy);
        float rA0 = sigmoid_fast(prx), rA1 = sigmoid_fast(pry);
        float zA0 = sigmoid_fast(pzx), zA1 = sigmoid_fast(pzy);
        u64 pnA = fma2(pack2(rA0, rA1), anA, fma2(xvA, win2, bin2));
        float pnx, pny;
        unpack2(pnA, pnx, pny);
        float nA0 = tanh_fast(pnx), nA1 = tanh_fast(pny);
        float hA0, hA1;
        unpack2(hA, hA0, hA1);
        hA0 = nA0 + zA0 * (hA0 - nA0);
        hA1 = nA1 + zA1 * (hA1 - nA1);
        hA = pack2(hA0, hA1);

        // pair B gates
        u64 prB = add2(fma2(xvB, wir2, bir2), arB);
        u64 pzB = add2(fma2(xvB, wiz2, biz2), azB);
        unpack2(prB, prx, pry);
        unpack2(pzB, pzx, pzy);
        float rB0 = sigmoid_fast(prx), rB1 = sigmoid_fast(pry);
        float zB0 = sigmoid_fast(pzx), zB1 = sigmoid_fast(pzy);
        u64 pnB = fma2(pack2(rB0, rB1), anB, fma2(xvB, win2, bin2));
        unpack2(pnB, pnx, pny);
        float nB0 = tanh_fast(pnx), nB1 = tanh_fast(pny);
        float hB0, hB1;
        unpack2(hB, hB0, hB1);
        hB0 = nB0 + zB0 * (hB0 - nB0);
        hB1 = nB1 + zB1 * (hB1 - nB1);
        hB = pack2(hB0, hB1);

        yq[0]  = hA;      // pair (b0, b0+1)
        yq[32] = hB;      // pair (b0+2, b0+3)
        yq += ystep;
        xvA = xnA;
        xvB = xnB;
    }
}

// ---------------------------------------------------------------------------
// Kernel 2: layer-1 forward input projection, TIME-PARALLEL, f32x2.
// One 32-lane warp per element pair: lane (half, j) accumulates gate rows
// {j, j+16, j+32} over 16 of the 32 input columns as FMA2 on u64 pairs
// loaded straight from g_y0p (no packing), then a shfl_xor(16) reduction.
// Half 0 stores element b0's float4, half 1 stores b0+1's.
// ---------------------------------------------------------------------------
__global__ void __launch_bounds__(128) l1_proj(
    const float* __restrict__ Wih, const float* __restrict__ bih)
{
    const int lane = threadIdx.x & 31;
    const int wrp = threadIdx.x >> 5;
    const int half = lane >> 4;
    const int j = lane & 15;
    const int p = blockIdx.x * 4 + wrp;      // pair index
    const int b0 = 2 * p;
    const int t0 = blockIdx.y * 32;

    const float* Wr = Wih + (j)      * 32 + half * 16;
    const float* Wz = Wih + (j + 16) * 32 + half * 16;
    const float* Wn = Wih + (j + 32) * 32 + half * 16;
    u64 w0[16], w1[16], w2[16];
#pragma unroll
    for (int k = 0; k < 16; ++k) {
        w0[k] = pack2(Wr[k], Wr[k]);
        w1[k] = pack2(Wz[k], Wz[k]);
        w2[k] = pack2(Wn[k], Wn[k]);
    }
    const u64 bg0 = half ? 0ull : pack2(bih[j],      bih[j]);
    const u64 bg1 = half ? 0ull : pack2(bih[j + 16], bih[j + 16]);
    const u64 bg2 = half ? 0ull : pack2(bih[j + 32], bih[j + 32]);

    const ulonglong2* yrow =
        (const ulonglong2*)(g_y0p + ((size_t)t0 * (BB / 2) + p) * 32) + half * 8;
    float4* go = g_gi + ((size_t)t0 * BB + (b0 + half)) * 16 + j;

#pragma unroll 2
    for (int t = 0; t < 32; ++t) {
        u64 v[16];
#pragma unroll
        for (int q = 0; q < 8; ++q) {
            ulonglong2 u = yrow[q];
            v[2 * q] = u.x;
            v[2 * q + 1] = u.y;
        }
        u64 a0 = bg0, a1 = bg1, a2 = bg2;
#pragma unroll
        for (int k = 0; k < 16; ++k) {
            a0 = fma2(w0[k], v[k], a0);
            a1 = fma2(w1[k], v[k], a1);
            a2 = fma2(w2[k], v[k], a2);
        }
        a0 = add2(a0, __shfl_xor_sync(0xFFFFFFFFu, a0, 16));
        a1 = add2(a1, __shfl_xor_sync(0xFFFFFFFFu, a1, 16));
        a2 = add2(a2, __shfl_xor_sync(0xFFFFFFFFu, a2, 16));

        float l0v, h0v, l1v, h1v, l2v, h2v;
        unpack2(a0, l0v, h0v);
        unpack2(a1, l1v, h1v);
        unpack2(a2, l2v, h2v);
        float4 o;
        o.x = half ? h0v : l0v;
        o.y = half ? h1v : l1v;
        o.z = half ? h2v : l2v;
        o.w = 0.0f;
        *go = o;

        yrow += (size_t)(BB / 2) * 16;     // next t (ulonglong2 units)
        go += (size_t)BB * 16;
    }
}

// ---------------------------------------------------------------------------
// Kernel 3: layer-1 forward recurrence (unchanged from R6: f32x2 pairs,
// depth-4 ring prefetch, fast activations). 171 us measured.
// ---------------------------------------------------------------------------
__global__ void __launch_bounds__(128) gru_l1f(
    const float* __restrict__ Whh, const float* __restrict__ bhh,
    float* __restrict__ out)
{
    const int tid = threadIdx.x;
    const int j = tid & 15;
    const int P = blockIdx.x * 8 + (tid >> 4);
    const int b0 = 2 * P;

    u64 wr2[16], wz2[16], wn2[16];
#pragma unroll
    for (int k = 0; k < 16; ++k) {
        float a = Whh[(j)      * 16 + k];
        float b = Whh[(j + 16) * 16 + k];
        float c = Whh[(j + 32) * 16 + k];
        wr2[k] = pack2(a, a);
        wz2[k] = pack2(b, b);
        wn2[k] = pack2(c, c);
    }
    const u64 bhr2 = pack2(bhh[j], bhh[j]);
    const u64 bhz2 = pack2(bhh[j + 16], bhh[j + 16]);
    const u64 bhn2 = pack2(bhh[j + 32], bhh[j + 32]);
    const u64 zero2 = 0ull;

    const size_t ts = (size_t)BB * 16;                 // float4 stride per t
    const float4* gp0 = g_gi + (size_t)b0 * 16 + j;
    const float4* gp1 = gp0 + 16;
    const float4* pf0 = gp0 + 4 * ts;
    const float4* pf1 = pf0 + 16;

    u64 rr[4], rz[4], rn[4];
#pragma unroll
    for (int q = 0; q < 4; ++q) {
        float4 A = gp0[(size_t)q * ts];
        float4 B = gp1[(size_t)q * ts];
        rr[q] = pack2(A.x, B.x);
        rz[q] = pack2(A.y, B.y);
        rn[q] = pack2(A.z, B.z);
    }

    u64 h2 = 0ull;
#pragma unroll 4
    for (int t = 0; t < TT; ++t) {
        const int sl = t & 3;
        u64 gr2 = rr[sl], gz2 = rz[sl], gn2 = rn[sl];
        if (t + 4 < TT) {
            float4 A = *pf0;
            float4 B = *pf1;
            rr[sl] = pack2(A.x, B.x);
            rz[sl] = pack2(A.y, B.y);
            rn[sl] = pack2(A.z, B.z);
        }
        pf0 += ts; pf1 += ts;

        u64 arA = bhr2, azA = bhz2, anA = bhn2;
        u64 arB = zero2, azB = zero2, anB = zero2;
#pragma unroll
        for (int k = 0; k < 8; ++k) {
            u64 hk = __shfl_sync(0xFFFFFFFFu, h2, k, 16);
            arA = fma2(wr2[k], hk, arA);
            azA = fma2(wz2[k], hk, azA);
            anA = fma2(wn2[k], hk, anA);
        }
#pragma unroll
        for (int k = 8; k < 16; ++k) {
            u64 hk = __shfl_sync(0xFFFFFFFFu, h2, k, 16);
            arB = fma2(wr2[k], hk, arB);
            azB = fma2(wz2[k], hk, azB);
            anB = fma2(wn2[k], hk, anB);
        }
        u64 pr = add2(gr2, add2(arA, arB));
        u64 pz = add2(gz2, add2(azA, azB));
        u64 an = add2(anA, anB);

        float prx, pry, pzx, pzy;
        unpack2(pr, prx, pry);
        unpack2(pz, pzx, pzy);
        float r0 = sigmoid_fast(prx), r1 = sigmoid_fast(pry);
        float z0 = sigmoid_fast(pzx), z1 = sigmoid_fast(pzy);

        u64 pn = fma2(pack2(r0, r1), an, gn2);
        float pnx, pny;
        unpack2(pn, pnx, pny);
        float n0 = tanh_fast(pnx), n1 = tanh_fast(pny);

        float h0, h1;
        unpack2(h2, h0, h1);
        h0 = n0 + z0 * (h0 - n0);
        h1 = n1 + z1 * (h1 - n1);
        h2 = pack2(h0, h1);
    }

    float h0, h1;
    unpack2(h2, h0, h1);
    out[b0 * 32 + j] = h0;
    out[(b0 + 1) * 32 + j] = h1;
}

// ---------------------------------------------------------------------------
// Kernel 4: layer-1 backward at position T-1 == one GRU step from h=0 on
// y0[T-1] (lax.scan reverse alignment). Reads pair-interleaved y0p.
// ---------------------------------------------------------------------------
__global__ void __launch_bounds__(128) gru_l1b(
    const float* __restrict__ Wih,
    const float* __restrict__ bih, const float* __restrict__ bhh,
    float* __restrict__ out)
{
    const int tid = threadIdx.x;
    const int j = tid & 15;
    const int e = tid >> 4;
    const int b = blockIdx.x * 8 + e;
    const int p = b >> 1;
    const int sel = b & 1;

    float wi0[32], wi1[32], wi2[32];
#pragma unroll
    for (int k = 0; k < 32; ++k) {
        wi0[k] = Wih[(j)      * 32 + k];
        wi1[k] = Wih[(j + 16) * 32 + k];
        wi2[k] = Wih[(j + 32) * 32 + k];
    }
    const float bir = bih[j], biz = bih[j + 16], bin_ = bih[j + 32];
    const float bhr = bhh[j], bhz = bhh[j + 16], bhn = bhh[j + 32];

    const ulonglong2* yrow =
        (const ulonglong2*)(g_y0p + ((size_t)(TT - 1) * (BB / 2) + p) * 32);
    ulonglong2 u2 = yrow[j];                       // cols 2j, 2j+1 (u64 pairs)
    float ax, bx, ay, by;
    unpack2(u2.x, ax, bx);
    unpack2(u2.y, ay, by);
    float2 my;
    my.x = sel ? bx : ax;
    my.y = sel ? by : ay;

    float ir = bir, iz = biz, in_ = bin_;
#pragma unroll
    for (int k = 0; k < 16; ++k) {
        float vx = __shfl_sync(0xFFFFFFFFu, my.x, k, 16);
        float vy = __shfl_sync(0xFFFFFFFFu, my.y, k, 16);
        ir  = fmaf(wi0[2 * k], vx, ir);  ir  = fmaf(wi0[2 * k + 1], vy, ir);
        iz  = fmaf(wi1[2 * k], vx, iz);  iz  = fmaf(wi1[2 * k + 1], vy, iz);
        in_ = fmaf(wi2[2 * k], vx, in_); in_ = fmaf(wi2[2 * k + 1], vy, in_);
    }
    float r = sigmoid_fast(ir + bhr);
    float z = sigmoid_fast(iz + bhz);
    float n = tanh_fast(fmaf(r, bhn, in_));
    out[b * 32 + 16 + j] = (1.0f - z) * n;   // h0 = 0
}

// ---------------------------------------------------------------------------
// Launch. Inputs: x, then (Wih, Whh, bih, bhh) for l0_f, l0_b, l1_f, l1_b.
// Order: l0, l1b, proj, l1f (last launch = ncu capture slot = l1f control).
// ---------------------------------------------------------------------------
extern "C" void kernel_launch(void* const* d_in, const int* in_sizes, int n_in,
                              void* d_out, int out_size) {
    const float* x = (const float*)d_in[0];

    dim3 g1(BB / 16, 2);
    gru_l0<<<g1, 64>>>(x,
        (const float*)d_in[1],  (const float*)d_in[2],
        (const float*)d_in[3],  (const float*)d_in[4],
        (const float*)d_in[5],  (const float*)d_in[6],
        (const float*)d_in[7],  (const float*)d_in[8]);

    gru_l1b<<<BB / 8, 128>>>(
        (const float*)d_in[13],
        (const float*)d_in[15], (const float*)d_in[16],
        (float*)d_out);

    dim3 g2(BB / 8, TT / 32);
    l1_proj<<<g2, 128>>>(
        (const float*)d_in[9],  (const float*)d_in[11]);

    gru_l1f<<<BB / 16, 128>>>(
        (const float*)d_in[10], (const float*)d_in[12],
        (float*)d_out);
}